// round 1
// baseline (speedup 1.0000x reference)
#include <cuda_runtime.h>
#include <cuda_bf16.h>
#include <cstddef>

// Problem constants
#define SS 2048
#define BB 64
#define DD 128
#define HH 128
#define GG 512   // 4*H

// 256 MB scratch for precomputed input gates: pre[t][b][512] = x@W_ih^T + b
__device__ float g_pre[(size_t)SS * BB * GG];

// ---------------------------------------------------------------------------
// Kernel P: pre = X @ W_ih^T + bias
// X: [S*B, 128] row-major, W_ih: [512, 128] row-major, pre: [S*B, 512]
// Tiles: BM=128 rows, BN=128 cols, full K=128 in shared.
// Shared layout transposed: Xs[k][i], Ws[k][j], padded row stride 132 floats
// (keeps 16B alignment for float4 reads).
// ---------------------------------------------------------------------------
#define PSTRIDE 132
__global__ void __launch_bounds__(256) pre_gemm_kernel(
    const float* __restrict__ X,
    const float* __restrict__ Wih,
    const float* __restrict__ bias)
{
    extern __shared__ float sm[];
    float* Xs = sm;                       // [128][PSTRIDE]
    float* Ws = sm + 128 * PSTRIDE;       // [128][PSTRIDE]

    const int tid = threadIdx.x;
    const int row0 = blockIdx.x * 128;
    const int col0 = blockIdx.y * 128;

    // Load X tile (rows row0..row0+127, k 0..127): consecutive tid -> consecutive k
    // Global coalesced; STS stride 132 floats -> 4-way conflict (one-time, OK).
    #pragma unroll
    for (int it = 0; it < 64; it++) {
        int idx = it * 256 + tid;
        int i = idx >> 7;
        int k = idx & 127;
        Xs[k * PSTRIDE + i] = X[(size_t)(row0 + i) * DD + k];
    }
    // Load W tile (cols col0..col0+127 of W_ih rows)
    #pragma unroll
    for (int it = 0; it < 64; it++) {
        int idx = it * 256 + tid;
        int j = idx >> 7;
        int k = idx & 127;
        Ws[k * PSTRIDE + j] = Wih[(size_t)(col0 + j) * DD + k];
    }
    __syncthreads();

    const int tx = tid & 15;   // col group
    const int ty = tid >> 4;   // row group

    float acc[8][8];
    #pragma unroll
    for (int i = 0; i < 8; i++)
        #pragma unroll
        for (int j = 0; j < 8; j++) acc[i][j] = 0.0f;

    #pragma unroll 4
    for (int k = 0; k < 128; k++) {
        float4 a0 = *(const float4*)&Xs[k * PSTRIDE + ty * 8];
        float4 a1 = *(const float4*)&Xs[k * PSTRIDE + ty * 8 + 4];
        float4 b0 = *(const float4*)&Ws[k * PSTRIDE + tx * 8];
        float4 b1 = *(const float4*)&Ws[k * PSTRIDE + tx * 8 + 4];
        float av[8] = {a0.x, a0.y, a0.z, a0.w, a1.x, a1.y, a1.z, a1.w};
        float bv[8] = {b0.x, b0.y, b0.z, b0.w, b1.x, b1.y, b1.z, b1.w};
        #pragma unroll
        for (int i = 0; i < 8; i++)
            #pragma unroll
            for (int j = 0; j < 8; j++)
                acc[i][j] += av[i] * bv[j];
    }

    // bias + store (float4, coalesced over tx)
    const int gcol = col0 + tx * 8;
    float bv8[8];
    #pragma unroll
    for (int j = 0; j < 8; j++) bv8[j] = bias[gcol + j];

    #pragma unroll
    for (int i = 0; i < 8; i++) {
        size_t r = (size_t)(row0 + ty * 8 + i);
        float* dst = g_pre + r * GG + gcol;
        float4 v0, v1;
        v0.x = acc[i][0] + bv8[0]; v0.y = acc[i][1] + bv8[1];
        v0.z = acc[i][2] + bv8[2]; v0.w = acc[i][3] + bv8[3];
        v1.x = acc[i][4] + bv8[4]; v1.y = acc[i][5] + bv8[5];
        v1.z = acc[i][6] + bv8[6]; v1.w = acc[i][7] + bv8[7];
        *(float4*)&dst[0] = v0;
        *(float4*)&dst[4] = v1;
    }
}

// ---------------------------------------------------------------------------
// Kernel R: reverse sequential scan. 1 block per batch element, 512 threads.
// Thread j owns gate row j. W_hh[j][0:64] in registers, W_hh[:][64:128] in
// shared (transposed float4 layout, conflict-free).
// ---------------------------------------------------------------------------
__device__ __forceinline__ float fast_sigmoid(float x) {
    return __fdividef(1.0f, 1.0f + __expf(-x));
}
__device__ __forceinline__ float fast_tanh(float x) {
    // tanh(x) = 1 - 2/(e^{2x}+1); correct limits at +/-inf via expf overflow
    return 1.0f - __fdividef(2.0f, __expf(2.0f * x) + 1.0f);
}

__global__ void __launch_bounds__(512, 1) lstm_rev_kernel(
    const float* __restrict__ timeArr,   // [S*B]
    const float* __restrict__ Whh,       // [512,128]
    const float* __restrict__ w_t,       // [128]
    const float* __restrict__ b_t,       // [128]
    float* __restrict__ out)             // outputs ++ h ++ c
{
    extern __shared__ float smem[];
    // layout: Wt4 (16*512 float4 = 128KB) | h_sh[128] | act[512]
    float4* Wt4 = (float4*)smem;                       // Wt4[c4*512 + j]
    float*  h_sh = smem + 16 * 512 * 4;                // 128 floats
    float*  act  = h_sh + 128;                         // 512 floats

    const int tid   = threadIdx.x;
    const int batch = blockIdx.x;

    // Register-resident first-half weights: W_hh[tid][0:64]
    float w0[64];
    #pragma unroll
    for (int c = 0; c < 64; c++)
        w0[c] = Whh[(size_t)tid * HH + c];

    // Shared second-half weights, transposed+packed:
    // Wt4[c4*512 + j] = W_hh[j][64+4c4 .. 64+4c4+3]
    #pragma unroll
    for (int c4 = 0; c4 < 16; c4++) {
        const float* src = Whh + (size_t)tid * HH + 64 + 4 * c4;
        Wt4[c4 * 512 + tid] = make_float4(src[0], src[1], src[2], src[3]);
    }

    // per-hidden decay params for combine threads
    float wt = 0.0f, bt = 0.0f, creg = 0.0f;
    if (tid < 128) {
        wt = w_t[tid];
        bt = b_t[tid];
        h_sh[tid] = 0.0f;
    }
    __syncthreads();

    const float* preP = g_pre + (size_t)batch * GG + tid;
    float pre_next = preP[(size_t)(SS - 1) * BB * GG];
    float tv_next  = timeArr[(size_t)(SS - 1) * BB + batch];

    const float4* h4 = (const float4*)h_sh;

    for (int t = SS - 1; t >= 0; t--) {
        const float pre_j = pre_next;
        const float tv    = tv_next;
        if (t > 0) {  // prefetch one step ahead (hides DRAM latency)
            pre_next = preP[(size_t)(t - 1) * BB * GG];
            tv_next  = timeArr[(size_t)(t - 1) * BB + batch];
        }

        // gates[j] = pre[j] + W_hh[j] . h
        float a0 = pre_j, a1 = 0.0f, a2 = 0.0f, a3 = 0.0f;
        #pragma unroll
        for (int c4 = 0; c4 < 16; c4++) {
            float4 hv = h4[c4];                       // broadcast
            a0 += w0[4 * c4 + 0] * hv.x;
            a1 += w0[4 * c4 + 1] * hv.y;
            a2 += w0[4 * c4 + 2] * hv.z;
            a3 += w0[4 * c4 + 3] * hv.w;
        }
        #pragma unroll
        for (int c4 = 0; c4 < 16; c4++) {
            float4 wv = Wt4[c4 * 512 + tid];          // conflict-free
            float4 hv = h4[16 + c4];                  // broadcast
            a0 += wv.x * hv.x;
            a1 += wv.y * hv.y;
            a2 += wv.z * hv.z;
            a3 += wv.w * hv.w;
        }
        float g = (a0 + a1) + (a2 + a3);

        // activation by quadrant (warp-uniform: quadrants are 128-thread aligned)
        float a;
        if ((tid >> 7) == 2) a = fast_tanh(g);
        else                 a = fast_sigmoid(g);
        act[tid] = a;
        __syncthreads();

        if (tid < 128) {
            float iv = act[tid];
            float fv = act[128 + tid];
            float gv = act[256 + tid];
            float ov = act[384 + tid];
            float dec = __expf(-fmaxf(tv * wt + bt, 0.0f));
            creg = fv * creg * dec + iv * gv;
            float hv = ov * fast_tanh(creg);
            h_sh[tid] = hv;
            out[(size_t)t * (BB * HH) + (size_t)batch * HH + tid] = hv;
        }
        __syncthreads();
    }

    // final state: h then c after the outputs block
    if (tid < 128) {
        size_t base = (size_t)SS * BB * HH;
        out[base + (size_t)batch * HH + tid] = h_sh[tid];
        out[base + (size_t)BB * HH + (size_t)batch * HH + tid] = creg;
    }
}

// ---------------------------------------------------------------------------
// Launch
// ---------------------------------------------------------------------------
extern "C" void kernel_launch(void* const* d_in, const int* in_sizes, int n_in,
                              void* d_out, int out_size)
{
    const float* X    = (const float*)d_in[0];  // input  (S,B,D)
    const float* Tm   = (const float*)d_in[1];  // time   (S,B,1)
    const float* Wih  = (const float*)d_in[2];  // (4H, D)
    const float* Whh  = (const float*)d_in[3];  // (4H, H)
    const float* bias = (const float*)d_in[4];  // (4H,)
    const float* wt   = (const float*)d_in[5];  // (H,)
    const float* bt   = (const float*)d_in[6];  // (H,)
    float* out = (float*)d_out;

    const int smemP = 2 * 128 * PSTRIDE * (int)sizeof(float);          // 135168 B
    const int smemR = (16 * 512 * 4 + 128 + 512) * (int)sizeof(float); // 133632 B
    cudaFuncSetAttribute(pre_gemm_kernel,
                         cudaFuncAttributeMaxDynamicSharedMemorySize, smemP);
    cudaFuncSetAttribute(lstm_rev_kernel,
                         cudaFuncAttributeMaxDynamicSharedMemorySize, smemR);

    // Kernel P: pre = X @ W_ih^T + b   over all (t,b)
    dim3 gridP((SS * BB) / 128, GG / 128);
    pre_gemm_kernel<<<gridP, 256, smemP>>>(X, Wih, bias);

    // Kernel R: reverse scan, one block per batch element
    lstm_rev_kernel<<<BB, 512, smemR>>>(Tm, Whh, wt, bt, out);
}